// round 10
// baseline (speedup 1.0000x reference)
#include <cuda_runtime.h>
#include <stdint.h>
#include <math.h>

#define BATCH 4
#define SEQ   2048
#define DIM   1024
#define MTOT  (BATCH * SEQ)   // 8192
#define SCALE 0.03125f        // 1/sqrt(1024)

// ---------------------------------------------------------------------------
// Device-global scratch (allocation-guard safe)
// ---------------------------------------------------------------------------
__device__ float g_Q[(size_t)MTOT * DIM];
__device__ float g_K[(size_t)MTOT * DIM];
__device__ float g_V[(size_t)MTOT * DIM];
__device__ float g_S[(size_t)BATCH * SEQ * SEQ];

__device__ int8_t g_xh[(size_t)MTOT * DIM];
__device__ int8_t g_xl[(size_t)MTOT * DIM];
__device__ float  g_sx[MTOT];
__device__ int8_t g_wh[(size_t)3 * DIM * DIM];    // W^T digits [w][n][k]
__device__ int8_t g_wl[(size_t)3 * DIM * DIM];
__device__ float  g_sw[3 * DIM];
__device__ int8_t g_qh[(size_t)MTOT * DIM];
__device__ int8_t g_ql[(size_t)MTOT * DIM];
__device__ float  g_sq[MTOT];
__device__ int8_t g_kh[(size_t)MTOT * DIM];
__device__ int8_t g_kl[(size_t)MTOT * DIM];
__device__ float  g_sk[MTOT];
__device__ int8_t g_ph[(size_t)BATCH * SEQ * SEQ];
__device__ int8_t g_pl[(size_t)BATCH * SEQ * SEQ];
__device__ float  g_sp[BATCH * SEQ];
__device__ int8_t g_vh[(size_t)BATCH * DIM * SEQ];  // V^T digits [b][d][s]
__device__ int8_t g_vl[(size_t)BATCH * DIM * SEQ];
__device__ float  g_sv[BATCH * DIM];

#define SWZ(o) ((o) ^ (((o) >> 3) & 0x70))
// K-chunk = 128 int8 cols -> 128B rows. Stage: Ah@0, Al@16K, Bh@32K, Bl@48K
#define STAGE_BYTES 65536

__device__ __forceinline__ uint32_t su32(const void* p) {
    uint32_t a;
    asm("{ .reg .u64 t; cvta.to.shared.u64 t, %1; cvt.u32.u64 %0, t; }"
        : "=r"(a) : "l"(p));
    return a;
}

__device__ __forceinline__ void ldsm4(uint32_t* r, uint32_t addr) {
    asm volatile("ldmatrix.sync.aligned.m8n8.x4.shared.b16 {%0,%1,%2,%3}, [%4];"
                 : "=r"(r[0]), "=r"(r[1]), "=r"(r[2]), "=r"(r[3]) : "r"(addr));
}

__device__ __forceinline__ void imma(int* d, const uint32_t* a,
                                     uint32_t b0, uint32_t b1) {
    asm volatile(
        "mma.sync.aligned.m16n8k32.row.col.s32.s8.s8.s32 "
        "{%0,%1,%2,%3}, {%4,%5,%6,%7}, {%8,%9}, {%0,%1,%2,%3};"
        : "+r"(d[0]), "+r"(d[1]), "+r"(d[2]), "+r"(d[3])
        : "r"(a[0]), "r"(a[1]), "r"(a[2]), "r"(a[3]), "r"(b0), "r"(b1));
}

__device__ __forceinline__ void cp_commit() {
    asm volatile("cp.async.commit_group;" ::: "memory");
}
__device__ __forceinline__ void cp_wait1() {
    asm volatile("cp.async.wait_group 1;" ::: "memory");
}
__device__ __forceinline__ void cp_wait0() {
    asm volatile("cp.async.wait_group 0;" ::: "memory");
}

// Async load of one 128x128 int8 tile (128B rows, SW128) into SMEM
__device__ __forceinline__ void async_tile(uint32_t dst, const int8_t* src,
                                           int ld, int tid) {
    #pragma unroll
    for (int t = 0; t < 4; t++) {
        const int idx = tid + t * 256;
        const int row = idx >> 3;
        const int c = idx & 7;
        const uint32_t d = dst + SWZ((uint32_t)(row * 128 + c * 16));
        asm volatile("cp.async.cg.shared.global [%0], [%1], 16;"
                     :: "r"(d), "l"(src + (size_t)row * ld + c * 16));
    }
}

__device__ __forceinline__ void load_chunk(uint32_t stage_base,
                                           const int8_t* Ah, const int8_t* Al,
                                           int lda,
                                           const int8_t* Bh, const int8_t* Bl,
                                           int ldb, int kc, int tid) {
    async_tile(stage_base,         Ah + (size_t)kc * 128, lda, tid);
    async_tile(stage_base + 16384, Al + (size_t)kc * 128, lda, tid);
    async_tile(stage_base + 32768, Bh + (size_t)kc * 128, ldb, tid);
    async_tile(stage_base + 49152, Bl + (size_t)kc * 128, ldb, tid);
    cp_commit();
}

// ---------------------------------------------------------------------------
// Warp K-chunk compute: 4 k32 steps, int8 two-digit, term-major.
// warp grid: wm in [0,4) -> 32 rows, wn in [0,2) -> 64 cols
// ---------------------------------------------------------------------------
__device__ __forceinline__ void compute_chunk(uint32_t stage_base,
                                              int acch[2][8][4],
                                              int accm[2][8][4], int lane,
                                              int wm, int wn) {
    const uint32_t ahi_b = stage_base;
    const uint32_t alo_b = stage_base + 16384;
    const uint32_t bhi_b = stage_base + 32768;
    const uint32_t blo_b = stage_base + 49152;
    const int ar = lane & 15;
    const int ac = (lane >> 4) * 16;
    const int br = ((lane >> 4) & 1) * 8 + (lane & 7);
    const int bc = ((lane >> 3) & 1) * 16;
    #pragma unroll
    for (int ks = 0; ks < 4; ks++) {
        uint32_t AH[2][4], AL[2][4], BH[4][4], BL[4][4];
        #pragma unroll
        for (int mt = 0; mt < 2; mt++) {
            const uint32_t off =
                SWZ((uint32_t)((wm * 32 + mt * 16 + ar) * 128 + ks * 32 + ac));
            ldsm4(AH[mt], ahi_b + off);
            ldsm4(AL[mt], alo_b + off);
        }
        #pragma unroll
        for (int p = 0; p < 4; p++) {
            const uint32_t off =
                SWZ((uint32_t)((wn * 64 + p * 16 + br) * 128 + ks * 32 + bc));
            ldsm4(BH[p], bhi_b + off);
            ldsm4(BL[p], blo_b + off);
        }
        #pragma unroll
        for (int mt = 0; mt < 2; mt++)
            #pragma unroll
            for (int nt = 0; nt < 8; nt++) {
                const int p = nt >> 1, h = (nt & 1) * 2;
                imma(acch[mt][nt], AH[mt], BH[p][h], BH[p][h + 1]);
            }
        #pragma unroll
        for (int mt = 0; mt < 2; mt++)
            #pragma unroll
            for (int nt = 0; nt < 8; nt++) {
                const int p = nt >> 1, h = (nt & 1) * 2;
                imma(accm[mt][nt], AH[mt], BL[p][h], BL[p][h + 1]);
            }
        #pragma unroll
        for (int mt = 0; mt < 2; mt++)
            #pragma unroll
            for (int nt = 0; nt < 8; nt++) {
                const int p = nt >> 1, h = (nt & 1) * 2;
                imma(accm[mt][nt], AL[mt], BH[p][h], BH[p][h + 1]);
            }
    }
}

// 2-stage double-buffered pipeline
__device__ __forceinline__ void gemm_pipeline(uint32_t smb, int nchunks,
                                              const int8_t* Ah, const int8_t* Al,
                                              int lda,
                                              const int8_t* Bh, const int8_t* Bl,
                                              int ldb, int acch[2][8][4],
                                              int accm[2][8][4], int tid,
                                              int lane, int wm, int wn) {
    load_chunk(smb, Ah, Al, lda, Bh, Bl, ldb, 0, tid);
    for (int kc = 0; kc < nchunks; kc++) {
        if (kc + 1 < nchunks) {
            load_chunk(smb + ((kc + 1) & 1) * STAGE_BYTES, Ah, Al, lda, Bh, Bl,
                       ldb, kc + 1, tid);
            cp_wait1();
        } else {
            cp_wait0();
        }
        __syncthreads();
        compute_chunk(smb + (kc & 1) * STAGE_BYTES, acch, accm, lane, wm, wn);
        __syncthreads();
    }
}

// ---------------------------------------------------------------------------
// Epilogue: combine digits with scales, store fp32. mode 1 = scores mask.
// ---------------------------------------------------------------------------
__device__ __forceinline__ void store_acc(int acch[2][8][4], int accm[2][8][4],
                                          float* dst, int ld, int m0, int n0,
                                          const float* sa, const float* sb,
                                          int mode, int lane, int wm, int wn) {
    #pragma unroll
    for (int mt = 0; mt < 2; mt++)
        #pragma unroll
        for (int nt = 0; nt < 8; nt++) {
            const int row = wm * 32 + mt * 16 + (lane >> 2);
            const int col = wn * 64 + nt * 8 + (lane & 3) * 2;
            const float sc0 = sb[col], sc1 = sb[col + 1];
            #pragma unroll
            for (int hh = 0; hh < 2; hh++) {
                const int r = row + hh * 8;
                const float sr = sa[r];
                float f0 = sr * sc0 *
                    ((float)acch[mt][nt][hh * 2 + 0] +
                     (float)accm[mt][nt][hh * 2 + 0] * 0.0078125f);
                float f1 = sr * sc1 *
                    ((float)acch[mt][nt][hh * 2 + 1] +
                     (float)accm[mt][nt][hh * 2 + 1] * 0.0078125f);
                if (mode == 1) {
                    const int q = m0 + r, k = n0 + col;
                    f0 = (k + 0 > q) ? -1e30f : f0 * SCALE;
                    f1 = (k + 1 > q) ? -1e30f : f1 * SCALE;
                }
                *(float2*)(dst + (size_t)(m0 + r) * ld + n0 + col) =
                    make_float2(f0, f1);
            }
        }
}

// ---------------------------------------------------------------------------
// Quantization prep kernels — ALL global arrays referenced in DEVICE code
// ---------------------------------------------------------------------------
__device__ __forceinline__ void q2(float a, float inv, int8_t* h, int8_t* l) {
    const float q = a * inv;
    const float qh = rintf(q);
    *h = (int8_t)(int)qh;
    *l = (int8_t)(int)rintf((q - qh) * 128.0f);
}

// One block per row; rowsel 0 = input x (via ptr), 1 = g_Q, 2 = g_K
__device__ __forceinline__ void quant_row_impl(const float* r, int8_t* qh,
                                               int8_t* ql, float* scale,
                                               int row) {
    const int tid = threadIdx.x;
    __shared__ float red[256];
    float m = 0.f;
    for (int i = tid; i < DIM; i += 256) m = fmaxf(m, fabsf(r[i]));
    red[tid] = m;
    __syncthreads();
    #pragma unroll
    for (int s = 128; s > 0; s >>= 1) {
        if (tid < s) red[tid] = fmaxf(red[tid], red[tid + s]);
        __syncthreads();
    }
    const float sa = fmaxf(red[0], 1e-20f) * (1.0f / 127.0f);
    if (tid == 0) scale[row] = sa;
    const float inv = 1.0f / sa;
    for (int i = tid; i < DIM; i += 256)
        q2(r[i], inv, &qh[(size_t)row * DIM + i], &ql[(size_t)row * DIM + i]);
}

__global__ void __launch_bounds__(256) quant_x(const float* __restrict__ x) {
    const int row = blockIdx.x;
    quant_row_impl(x + (size_t)row * DIM, g_xh, g_xl, g_sx, row);
}

__global__ void __launch_bounds__(256) quant_qk() {
    const int row = blockIdx.x;
    if (blockIdx.y == 0)
        quant_row_impl(g_Q + (size_t)row * DIM, g_qh, g_ql, g_sq, row);
    else
        quant_row_impl(g_K + (size_t)row * DIM, g_kh, g_kl, g_sk, row);
}

__global__ void colmax_w(const float* __restrict__ Wq,
                         const float* __restrict__ Wk,
                         const float* __restrict__ Wv) {
    const int w = blockIdx.y;
    const float* W = (w == 0) ? Wq : (w == 1) ? Wk : Wv;
    const int n = blockIdx.x * 256 + threadIdx.x;
    float m = 0.f;
    for (int k = 0; k < DIM; k++) m = fmaxf(m, fabsf(W[(size_t)k * DIM + n]));
    g_sw[w * DIM + n] = fmaxf(m, 1e-20f) * (1.0f / 127.0f);
}

__global__ void colmax_v() {
    const int b = blockIdx.y;
    const int d = blockIdx.x * 256 + threadIdx.x;
    const float* V = g_V + (size_t)b * SEQ * DIM;
    float m = 0.f;
    for (int s = 0; s < SEQ; s++) m = fmaxf(m, fabsf(V[(size_t)s * DIM + d]));
    g_sv[b * DIM + d] = fmaxf(m, 1e-20f) * (1.0f / 127.0f);
}

// Transpose + quantize W -> W^T digits [w][n][k]
__global__ void prep_wq(const float* __restrict__ Wq,
                        const float* __restrict__ Wk,
                        const float* __restrict__ Wv) {
    __shared__ float t[32][33];
    const int w = blockIdx.z;
    const float* W = (w == 0) ? Wq : (w == 1) ? Wk : Wv;
    const int tx = threadIdx.x, ty = threadIdx.y;
    const int n0 = blockIdx.x * 32, k0 = blockIdx.y * 32;
    #pragma unroll
    for (int i = 0; i < 4; i++)
        t[ty + 8 * i][tx] = W[(size_t)(k0 + ty + 8 * i) * DIM + n0 + tx];
    __syncthreads();
    #pragma unroll
    for (int i = 0; i < 4; i++) {
        const int n = n0 + ty + 8 * i;
        const float inv = 1.0f / g_sw[w * DIM + n];
        const size_t o = (size_t)w * DIM * DIM + (size_t)n * DIM + k0 + tx;
        q2(t[tx][ty + 8 * i], inv, &g_wh[o], &g_wl[o]);
    }
}

// Transpose + quantize V -> V^T digits [b][d][s]
__global__ void prep_vq() {
    __shared__ float t[32][33];
    const int b = blockIdx.z;
    const float* V = g_V + (size_t)b * SEQ * DIM;
    const int tx = threadIdx.x, ty = threadIdx.y;
    const int d0 = blockIdx.x * 32, s0 = blockIdx.y * 32;
    #pragma unroll
    for (int i = 0; i < 4; i++)
        t[ty + 8 * i][tx] = V[(size_t)(s0 + ty + 8 * i) * DIM + d0 + tx];
    __syncthreads();
    #pragma unroll
    for (int i = 0; i < 4; i++) {
        const int d = d0 + ty + 8 * i;
        const float inv = 1.0f / g_sv[b * DIM + d];
        const size_t o = (size_t)b * DIM * SEQ + (size_t)d * SEQ + s0 + tx;
        q2(t[tx][ty + 8 * i], inv, &g_vh[o], &g_vl[o]);
    }
}

// ---------------------------------------------------------------------------
// GEMM 1: QKV projection -> fp32 Q/K/V
// ---------------------------------------------------------------------------
__global__ void __launch_bounds__(256) qkv_imma() {
    extern __shared__ uint8_t dsm[];
    const uint32_t smb = su32(dsm);
    const int tid = threadIdx.x;
    const int lane = tid & 31;
    const int wid = tid >> 5;
    const int wm = wid & 3, wn = wid >> 2;

    const int w = blockIdx.z;
    const int m0 = blockIdx.y * 128;
    const int n0 = blockIdx.x * 128;
    const int8_t* Ah = g_xh + (size_t)m0 * DIM;
    const int8_t* Al = g_xl + (size_t)m0 * DIM;
    const int8_t* Bh = g_wh + (size_t)w * DIM * DIM + (size_t)n0 * DIM;
    const int8_t* Bl = g_wl + (size_t)w * DIM * DIM + (size_t)n0 * DIM;
    float* C = (w == 0) ? g_Q : (w == 1) ? g_K : g_V;

    int acch[2][8][4] = {}, accm[2][8][4] = {};
    gemm_pipeline(smb, DIM / 128, Ah, Al, DIM, Bh, Bl, DIM, acch, accm, tid,
                  lane, wm, wn);
    store_acc(acch, accm, C, DIM, m0, n0, g_sx + m0, g_sw + w * DIM + n0, 0,
              lane, wm, wn);
}

// ---------------------------------------------------------------------------
// GEMM 2: scores = scale * Q @ K^T, causal mask fused
// ---------------------------------------------------------------------------
__global__ void __launch_bounds__(256) scores_imma() {
    const int kt = blockIdx.x;
    const int qt = blockIdx.y;
    if (kt > qt) return;
    extern __shared__ uint8_t dsm[];
    const uint32_t smb = su32(dsm);
    const int tid = threadIdx.x;
    const int lane = tid & 31;
    const int wid = tid >> 5;
    const int wm = wid & 3, wn = wid >> 2;

    const int b = blockIdx.z;
    const int m0 = qt * 128;
    const int n0 = kt * 128;
    const int8_t* Ah = g_qh + (size_t)(b * SEQ + m0) * DIM;
    const int8_t* Al = g_ql + (size_t)(b * SEQ + m0) * DIM;
    const int8_t* Bh = g_kh + (size_t)(b * SEQ + n0) * DIM;
    const int8_t* Bl = g_kl + (size_t)(b * SEQ + n0) * DIM;

    int acch[2][8][4] = {}, accm[2][8][4] = {};
    gemm_pipeline(smb, DIM / 128, Ah, Al, DIM, Bh, Bl, DIM, acch, accm, tid,
                  lane, wm, wn);
    store_acc(acch, accm, g_S + (size_t)b * SEQ * SEQ, SEQ, m0, n0,
              g_sq + b * SEQ + m0, g_sk + b * SEQ + n0, 1, lane, wm, wn);
}

// ---------------------------------------------------------------------------
// Kernel 3: row softmax -> int8 P digits + row scale
// ---------------------------------------------------------------------------
__global__ void __launch_bounds__(256) softmax_rows() {
    const int q = blockIdx.x;
    const int b = blockIdx.y;
    const size_t base = (size_t)b * SEQ * SEQ + (size_t)q * SEQ;
    const float* row = g_S + base;
    const int L = ((q >> 7) + 1) << 7;

    const int tid = threadIdx.x;
    __shared__ float red[256];

    float vals[8];
    int cnt = 0;
    float m = -1e30f;
    for (int idx = tid; idx < L; idx += 256) {
        vals[cnt] = row[idx];
        m = fmaxf(m, vals[cnt]);
        cnt++;
    }
    red[tid] = m;
    __syncthreads();
    #pragma unroll
    for (int s = 128; s > 0; s >>= 1) {
        if (tid < s) red[tid] = fmaxf(red[tid], red[tid + s]);
        __syncthreads();
    }
    const float M = red[0];
    __syncthreads();

    float sum = 0.f;
    for (int i = 0; i < cnt; i++) {
        vals[i] = __expf(vals[i] - M);
        sum += vals[i];
    }
    red[tid] = sum;
    __syncthreads();
    #pragma unroll
    for (int s = 128; s > 0; s >>= 1) {
        if (tid < s) red[tid] += red[tid + s];
        __syncthreads();
    }
    const float inv = 1.0f / red[0];

    // p = vals*inv; max val = 1 -> sp = inv/127, digits of vals*127
    if (tid == 0) g_sp[b * SEQ + q] = inv * (1.0f / 127.0f);
    cnt = 0;
    for (int idx = tid; idx < L; idx += 256) {
        const float v127 = vals[cnt++] * 127.0f;
        const float qh = rintf(v127);
        g_ph[base + idx] = (int8_t)(int)qh;
        g_pl[base + idx] = (int8_t)(int)rintf((v127 - qh) * 128.0f);
    }
}

// ---------------------------------------------------------------------------
// GEMM 4: O = P @ V, causal K-extent, heavy tiles first
// ---------------------------------------------------------------------------
__global__ void __launch_bounds__(256) pv_imma(float* __restrict__ out) {
    extern __shared__ uint8_t dsm[];
    const uint32_t smb = su32(dsm);
    const int tid = threadIdx.x;
    const int lane = tid & 31;
    const int wid = tid >> 5;
    const int wm = wid & 3, wn = wid >> 2;

    const int et = blockIdx.x;
    const int qt = (SEQ / 128 - 1) - blockIdx.y;   // heavy tiles first
    const int b  = blockIdx.z;
    const int m0 = qt * 128;
    const int n0 = et * 128;
    const int nchunks = qt + 1;   // K-extent (qt+1)*128 / 128

    const int8_t* Ah = g_ph + (size_t)b * SEQ * SEQ + (size_t)m0 * SEQ;
    const int8_t* Al = g_pl + (size_t)b * SEQ * SEQ + (size_t)m0 * SEQ;
    const int8_t* Bh = g_vh + (size_t)b * DIM * SEQ + (size_t)n0 * SEQ;
    const int8_t* Bl = g_vl + (size_t)b * DIM * SEQ + (size_t)n0 * SEQ;

    int acch[2][8][4] = {}, accm[2][8][4] = {};
    gemm_pipeline(smb, nchunks, Ah, Al, SEQ, Bh, Bl, SEQ, acch, accm, tid,
                  lane, wm, wn);
    store_acc(acch, accm, out + (size_t)b * SEQ * DIM, DIM, m0, n0,
              g_sp + b * SEQ + m0, g_sv + b * DIM + n0, 0, lane, wm, wn);
}

// ---------------------------------------------------------------------------
extern "C" void kernel_launch(void* const* d_in, const int* in_sizes, int n_in,
                              void* d_out, int out_size) {
    const float* x  = (const float*)d_in[0];
    const float* Wq = (const float*)d_in[1];
    const float* Wk = (const float*)d_in[2];
    const float* Wv = (const float*)d_in[3];
    float* out = (float*)d_out;

    const int DSM = 2 * STAGE_BYTES;  // 128KB
    static bool attr_done = false;
    if (!attr_done) {
        cudaFuncSetAttribute(qkv_imma, cudaFuncAttributeMaxDynamicSharedMemorySize, DSM);
        cudaFuncSetAttribute(scores_imma, cudaFuncAttributeMaxDynamicSharedMemorySize, DSM);
        cudaFuncSetAttribute(pv_imma, cudaFuncAttributeMaxDynamicSharedMemorySize, DSM);
        attr_done = true;
    }

    quant_x<<<MTOT, 256>>>(x);
    colmax_w<<<dim3(DIM / 256, 3), 256>>>(Wq, Wk, Wv);
    prep_wq<<<dim3(DIM / 32, DIM / 32, 3), dim3(32, 8)>>>(Wq, Wk, Wv);
    qkv_imma<<<dim3(DIM / 128, MTOT / 128, 3), 256, DSM>>>();
    quant_qk<<<dim3(MTOT, 2), 256>>>();
    colmax_v<<<dim3(DIM / 256, BATCH), 256>>>();
    prep_vq<<<dim3(DIM / 32, SEQ / 32, BATCH), dim3(32, 8)>>>();
    scores_imma<<<dim3(SEQ / 128, SEQ / 128, BATCH), 256, DSM>>>();
    softmax_rows<<<dim3(SEQ, BATCH), 256>>>();
    pv_imma<<<dim3(DIM / 128, SEQ / 128, BATCH), 256, DSM>>>(out);
}

// round 11
// speedup vs baseline: 3.6083x; 3.6083x over previous
#include <cuda_runtime.h>
#include <stdint.h>
#include <math.h>

#define BATCH 4
#define SEQ   2048
#define DIM   1024
#define MTOT  (BATCH * SEQ)   // 8192
#define SCALE 0.03125f        // 1/sqrt(1024)

// ---------------------------------------------------------------------------
// Device-global scratch (allocation-guard safe) — all fp32 (tf32-rounded)
// ---------------------------------------------------------------------------
__device__ float g_X [(size_t)MTOT * DIM];                 // rounded x [m][k]
__device__ float g_WT[(size_t)3 * DIM * DIM];              // rounded W^T [w][n][k]
__device__ float g_Q [(size_t)MTOT * DIM];                 // rounded
__device__ float g_K [(size_t)MTOT * DIM];                 // rounded
__device__ float g_V [(size_t)MTOT * DIM];                 // rounded
__device__ float g_VT[(size_t)BATCH * DIM * SEQ];          // V^T [b][d][s]
__device__ float g_S [(size_t)BATCH * SEQ * SEQ];          // raw scores
__device__ float g_P [(size_t)BATCH * SEQ * SEQ];          // rounded softmax

#define SWZ(o) ((o) ^ (((o) >> 3) & 0x70))
// K-chunk = 32 tf32 cols -> 128B rows. Stage: A@0 (16K), B@16K. 32KB/stage.
#define STAGE_BYTES 32768
#define NSTAGE 4

__device__ __forceinline__ uint32_t su32(const void* p) {
    uint32_t a;
    asm("{ .reg .u64 t; cvta.to.shared.u64 t, %1; cvt.u32.u64 %0, t; }"
        : "=r"(a) : "l"(p));
    return a;
}

__device__ __forceinline__ float totf(float v) {
    uint32_t r;
    asm("cvt.rna.tf32.f32 %0, %1;" : "=r"(r) : "f"(v));
    return __uint_as_float(r);
}

__device__ __forceinline__ void ldsm4(uint32_t* r, uint32_t addr) {
    asm volatile("ldmatrix.sync.aligned.m8n8.x4.shared.b16 {%0,%1,%2,%3}, [%4];"
                 : "=r"(r[0]), "=r"(r[1]), "=r"(r[2]), "=r"(r[3]) : "r"(addr));
}

__device__ __forceinline__ void mma_tf32(float* d, const uint32_t* a,
                                         uint32_t b0, uint32_t b1) {
    asm volatile(
        "mma.sync.aligned.m16n8k8.row.col.f32.tf32.tf32.f32 "
        "{%0,%1,%2,%3}, {%4,%5,%6,%7}, {%8,%9}, {%0,%1,%2,%3};"
        : "+f"(d[0]), "+f"(d[1]), "+f"(d[2]), "+f"(d[3])
        : "r"(a[0]), "r"(a[1]), "r"(a[2]), "r"(a[3]), "r"(b0), "r"(b1));
}

__device__ __forceinline__ void cp_commit() {
    asm volatile("cp.async.commit_group;" ::: "memory");
}
__device__ __forceinline__ void cp_waitN(int tailcase) {
    // tailcase computed by caller; compile-time dispatch below
    if (tailcase == 2)      asm volatile("cp.async.wait_group 2;" ::: "memory");
    else if (tailcase == 1) asm volatile("cp.async.wait_group 1;" ::: "memory");
    else                    asm volatile("cp.async.wait_group 0;" ::: "memory");
}

// Async load of one 128-row x 32-col fp32 tile (128B rows, SW128) into SMEM
__device__ __forceinline__ void async_tile(uint32_t dst, const float* src,
                                           int ld, int tid) {
    #pragma unroll
    for (int t = 0; t < 4; t++) {
        const int idx = tid + t * 256;
        const int row = idx >> 3;
        const int c = idx & 7;
        const uint32_t d = dst + SWZ((uint32_t)(row * 128 + c * 16));
        asm volatile("cp.async.cg.shared.global [%0], [%1], 16;"
                     :: "r"(d), "l"(src + (size_t)row * ld + c * 4));
    }
}

__device__ __forceinline__ void load_chunk(uint32_t stage_base,
                                           const float* A, int lda,
                                           const float* B, int ldb,
                                           int kc, int tid) {
    async_tile(stage_base,         A + (size_t)kc * 32, lda, tid);
    async_tile(stage_base + 16384, B + (size_t)kc * 32, ldb, tid);
    cp_commit();
}

// ---------------------------------------------------------------------------
// Warp K-chunk compute: 4 k8 steps, single-pass tf32.
// warp grid: wm in [0,4) -> 32 rows, wn in [0,2) -> 64 cols
// Per ks: 4 B ldsm.x4 (-> 8 n8 frags) + per mt: 1 A ldsm.x4 + 8 MMAs.
// ---------------------------------------------------------------------------
__device__ __forceinline__ void compute_chunk(uint32_t stage_base,
                                              float acc[2][8][4], int lane,
                                              int wm, int wn) {
    const uint32_t a_b = stage_base;
    const uint32_t b_b = stage_base + 16384;
    const int ar = lane & 15;
    const int xo = (lane >> 4) * 16;
    #pragma unroll
    for (int ks = 0; ks < 4; ks++) {
        uint32_t B[4][4];
        #pragma unroll
        for (int p = 0; p < 4; p++)
            ldsm4(B[p], b_b + SWZ((uint32_t)((wn * 64 + p * 16 + ar) * 128 +
                                             ks * 32 + xo)));
        #pragma unroll
        for (int mt = 0; mt < 2; mt++) {
            uint32_t A[4];
            ldsm4(A, a_b + SWZ((uint32_t)((wm * 32 + mt * 16 + ar) * 128 +
                                          ks * 32 + xo)));
            #pragma unroll
            for (int nt = 0; nt < 8; nt++) {
                const int p = nt >> 1, h = nt & 1;
                // frag (p, h): {r[h], r[2+h]} of B[p]
                mma_tf32(acc[mt][nt], A, B[p][h], B[p][2 + h]);
            }
        }
    }
}

// 4-stage pipeline, 3-deep prefetch, ONE barrier per chunk.
// Order per iter: wait(kc ready, own groups) -> barrier (publish kc to all,
// retire compute kc-1) -> issue load kc+3 (stage (kc-1)%4, now safe) -> compute.
__device__ __forceinline__ void gemm_pipeline(uint32_t smb, int nchunks,
                                              const float* A, int lda,
                                              const float* B, int ldb,
                                              float acc[2][8][4], int tid,
                                              int lane, int wm, int wn) {
    load_chunk(smb,                   A, lda, B, ldb, 0, tid);
    if (1 < nchunks) load_chunk(smb + STAGE_BYTES,     A, lda, B, ldb, 1, tid);
    if (2 < nchunks) load_chunk(smb + 2 * STAGE_BYTES, A, lda, B, ldb, 2, tid);
    for (int kc = 0; kc < nchunks; kc++) {
        if (kc + 2 < nchunks)      cp_waitN(2);
        else if (kc + 1 < nchunks) cp_waitN(1);
        else                       cp_waitN(0);
        __syncthreads();
        if (kc + 3 < nchunks)
            load_chunk(smb + ((kc + 3) & 3) * STAGE_BYTES, A, lda, B, ldb,
                       kc + 3, tid);
        compute_chunk(smb + (kc & 3) * STAGE_BYTES, acc, lane, wm, wn);
    }
}

// ---------------------------------------------------------------------------
// Epilogue. mode 0: plain fp32; mode 1: scores mask+scale; mode 2: tf32 round
// ---------------------------------------------------------------------------
__device__ __forceinline__ void store_acc(float acc[2][8][4], float* dst,
                                          int ld, int m0, int n0, int mode,
                                          int lane, int wm, int wn) {
    #pragma unroll
    for (int mt = 0; mt < 2; mt++)
        #pragma unroll
        for (int nt = 0; nt < 8; nt++) {
            const int row = m0 + wm * 32 + mt * 16 + (lane >> 2);
            const int col = n0 + wn * 64 + nt * 8 + (lane & 3) * 2;
            float2 v0 = {acc[mt][nt][0], acc[mt][nt][1]};
            float2 v1 = {acc[mt][nt][2], acc[mt][nt][3]};
            if (mode == 1) {
                v0.x = (col + 0 > row) ? -1e30f : v0.x * SCALE;
                v0.y = (col + 1 > row) ? -1e30f : v0.y * SCALE;
                v1.x = (col + 0 > row + 8) ? -1e30f : v1.x * SCALE;
                v1.y = (col + 1 > row + 8) ? -1e30f : v1.y * SCALE;
            } else if (mode == 2) {
                v0.x = totf(v0.x); v0.y = totf(v0.y);
                v1.x = totf(v1.x); v1.y = totf(v1.y);
            }
            *(float2*)(dst + (size_t)row * ld + col) = v0;
            *(float2*)(dst + (size_t)(row + 8) * ld + col) = v1;
        }
}

// ---------------------------------------------------------------------------
// Prep kernels
// ---------------------------------------------------------------------------
__global__ void round_x(const float4* __restrict__ x) {
    const size_t i = (size_t)blockIdx.x * blockDim.x + threadIdx.x;
    float4 v = x[i];
    v.x = totf(v.x); v.y = totf(v.y); v.z = totf(v.z); v.w = totf(v.w);
    ((float4*)g_X)[i] = v;
}

__global__ void prep_w(const float* __restrict__ Wq, const float* __restrict__ Wk,
                       const float* __restrict__ Wv) {
    __shared__ float t[32][33];
    const int w = blockIdx.z;
    const float* W = (w == 0) ? Wq : (w == 1) ? Wk : Wv;
    float* o = g_WT + (size_t)w * DIM * DIM;
    const int tx = threadIdx.x, ty = threadIdx.y;
    const int n0 = blockIdx.x * 32, k0 = blockIdx.y * 32;
    #pragma unroll
    for (int i = 0; i < 4; i++)
        t[ty + 8 * i][tx] = W[(size_t)(k0 + ty + 8 * i) * DIM + n0 + tx];
    __syncthreads();
    #pragma unroll
    for (int i = 0; i < 4; i++)
        o[(size_t)(n0 + ty + 8 * i) * DIM + k0 + tx] = totf(t[tx][ty + 8 * i]);
}

__global__ void prep_vT() {
    __shared__ float t[32][33];
    const int b = blockIdx.z;
    const float* V = g_V + (size_t)b * SEQ * DIM;
    float* o = g_VT + (size_t)b * DIM * SEQ;
    const int tx = threadIdx.x, ty = threadIdx.y;
    const int d0 = blockIdx.x * 32, s0 = blockIdx.y * 32;
    #pragma unroll
    for (int i = 0; i < 4; i++)
        t[ty + 8 * i][tx] = V[(size_t)(s0 + ty + 8 * i) * DIM + d0 + tx];
    __syncthreads();
    #pragma unroll
    for (int i = 0; i < 4; i++)
        o[(size_t)(d0 + ty + 8 * i) * SEQ + s0 + tx] = t[tx][ty + 8 * i];
}

// ---------------------------------------------------------------------------
// GEMM 1: QKV projection -> tf32-rounded Q/K/V
// ---------------------------------------------------------------------------
__global__ void __launch_bounds__(256) qkv_tf() {
    extern __shared__ uint8_t dsm[];
    const uint32_t smb = su32(dsm);
    const int tid = threadIdx.x;
    const int lane = tid & 31;
    const int wid = tid >> 5;
    const int wm = wid & 3, wn = wid >> 2;

    const int w = blockIdx.z;
    const int m0 = blockIdx.y * 128;
    const int n0 = blockIdx.x * 128;
    const float* A = g_X + (size_t)m0 * DIM;
    const float* B = g_WT + (size_t)w * DIM * DIM + (size_t)n0 * DIM;
    float* C = (w == 0) ? g_Q : (w == 1) ? g_K : g_V;

    float acc[2][8][4] = {};
    gemm_pipeline(smb, DIM / 32, A, DIM, B, DIM, acc, tid, lane, wm, wn);
    store_acc(acc, C, DIM, m0, n0, 2, lane, wm, wn);
}

// ---------------------------------------------------------------------------
// GEMM 2: scores = scale * Q @ K^T, causal mask fused
// ---------------------------------------------------------------------------
__global__ void __launch_bounds__(256) scores_tf() {
    const int kt = blockIdx.x;
    const int qt = blockIdx.y;
    if (kt > qt) return;
    extern __shared__ uint8_t dsm[];
    const uint32_t smb = su32(dsm);
    const int tid = threadIdx.x;
    const int lane = tid & 31;
    const int wid = tid >> 5;
    const int wm = wid & 3, wn = wid >> 2;

    const int b = blockIdx.z;
    const int m0 = qt * 128;
    const int n0 = kt * 128;
    const float* A = g_Q + (size_t)(b * SEQ + m0) * DIM;
    const float* B = g_K + (size_t)(b * SEQ + n0) * DIM;

    float acc[2][8][4] = {};
    gemm_pipeline(smb, DIM / 32, A, DIM, B, DIM, acc, tid, lane, wm, wn);
    store_acc(acc, g_S + (size_t)b * SEQ * SEQ, SEQ, m0, n0, 1, lane, wm, wn);
}

// ---------------------------------------------------------------------------
// Kernel 3: row softmax -> tf32-rounded P
// ---------------------------------------------------------------------------
__global__ void __launch_bounds__(256) softmax_rows() {
    const int q = blockIdx.x;
    const int b = blockIdx.y;
    const size_t base = (size_t)b * SEQ * SEQ + (size_t)q * SEQ;
    const float* row = g_S + base;
    const int L = ((q >> 7) + 1) << 7;

    const int tid = threadIdx.x;
    __shared__ float red[256];

    float vals[8];
    int cnt = 0;
    float m = -1e30f;
    for (int idx = tid; idx < L; idx += 256) {
        vals[cnt] = row[idx];
        m = fmaxf(m, vals[cnt]);
        cnt++;
    }
    red[tid] = m;
    __syncthreads();
    #pragma unroll
    for (int s = 128; s > 0; s >>= 1) {
        if (tid < s) red[tid] = fmaxf(red[tid], red[tid + s]);
        __syncthreads();
    }
    const float M = red[0];
    __syncthreads();

    float sum = 0.f;
    for (int i = 0; i < cnt; i++) {
        vals[i] = __expf(vals[i] - M);
        sum += vals[i];
    }
    red[tid] = sum;
    __syncthreads();
    #pragma unroll
    for (int s = 128; s > 0; s >>= 1) {
        if (tid < s) red[tid] += red[tid + s];
        __syncthreads();
    }
    const float inv = 1.0f / red[0];

    cnt = 0;
    for (int idx = tid; idx < L; idx += 256)
        g_P[base + idx] = totf(vals[cnt++] * inv);
}

// ---------------------------------------------------------------------------
// GEMM 4: O = P @ V, causal K-extent, heavy q-tiles first
// ---------------------------------------------------------------------------
__global__ void __launch_bounds__(256) pv_tf(float* __restrict__ out) {
    extern __shared__ uint8_t dsm[];
    const uint32_t smb = su32(dsm);
    const int tid = threadIdx.x;
    const int lane = tid & 31;
    const int wid = tid >> 5;
    const int wm = wid & 3, wn = wid >> 2;

    const int et = blockIdx.x;
    const int qt = (SEQ / 128 - 1) - blockIdx.y;   // heavy tiles first
    const int b  = blockIdx.z;
    const int m0 = qt * 128;
    const int n0 = et * 128;
    const int nchunks = (qt + 1) * 4;   // K-extent (qt+1)*128 / 32

    const float* A = g_P + (size_t)b * SEQ * SEQ + (size_t)m0 * SEQ;
    const float* B = g_VT + (size_t)b * DIM * SEQ + (size_t)n0 * SEQ;

    float acc[2][8][4] = {};
    gemm_pipeline(smb, nchunks, A, SEQ, B, SEQ, acc, tid, lane, wm, wn);
    store_acc(acc, out + (size_t)b * SEQ * DIM, DIM, m0, n0, 0, lane, wm, wn);
}

// ---------------------------------------------------------------------------
extern "C" void kernel_launch(void* const* d_in, const int* in_sizes, int n_in,
                              void* d_out, int out_size) {
    const float* x  = (const float*)d_in[0];
    const float* Wq = (const float*)d_in[1];
    const float* Wk = (const float*)d_in[2];
    const float* Wv = (const float*)d_in[3];
    float* out = (float*)d_out;

    const int DSM = NSTAGE * STAGE_BYTES;  // 128KB
    static bool attr_done = false;
    if (!attr_done) {
        cudaFuncSetAttribute(qkv_tf, cudaFuncAttributeMaxDynamicSharedMemorySize, DSM);
        cudaFuncSetAttribute(scores_tf, cudaFuncAttributeMaxDynamicSharedMemorySize, DSM);
        cudaFuncSetAttribute(pv_tf, cudaFuncAttributeMaxDynamicSharedMemorySize, DSM);
        attr_done = true;
    }

    round_x<<<(MTOT * DIM / 4) / 256, 256>>>((const float4*)x);
    prep_w<<<dim3(DIM / 32, DIM / 32, 3), dim3(32, 8)>>>(Wq, Wk, Wv);
    qkv_tf<<<dim3(DIM / 128, MTOT / 128, 3), 256, DSM>>>();
    prep_vT<<<dim3(DIM / 32, SEQ / 32, BATCH), dim3(32, 8)>>>();
    scores_tf<<<dim3(SEQ / 128, SEQ / 128, BATCH), 256, DSM>>>();
    softmax_rows<<<dim3(SEQ, BATCH), 256>>>();
    pv_tf<<<dim3(DIM / 128, SEQ / 128, BATCH), 256, DSM>>>(out);
}

// round 13
// speedup vs baseline: 3.8162x; 1.0576x over previous
#include <cuda_runtime.h>
#include <stdint.h>
#include <math.h>

#define BATCH 4
#define SEQ   2048
#define DIM   1024
#define MTOT  (BATCH * SEQ)   // 8192
#define SCALE 0.03125f        // 1/sqrt(1024)

// ---------------------------------------------------------------------------
// Device-global scratch (allocation-guard safe) — all fp32 (tf32-rounded)
// ---------------------------------------------------------------------------
__device__ float g_X [(size_t)MTOT * DIM];                 // rounded x [m][k]
__device__ float g_WT[(size_t)3 * DIM * DIM];              // rounded W^T [w][n][k]
__device__ float g_Q [(size_t)MTOT * DIM];                 // rounded
__device__ float g_K [(size_t)MTOT * DIM];                 // rounded
__device__ float g_V [(size_t)MTOT * DIM];                 // rounded
__device__ float g_VT[(size_t)BATCH * DIM * SEQ];          // V^T [b][d][s]
__device__ float g_S [(size_t)BATCH * SEQ * SEQ];          // raw scores
__device__ float g_P [(size_t)BATCH * SEQ * SEQ];          // rounded softmax

#define SWZ(o) ((o) ^ (((o) >> 3) & 0x70))
// K-chunk = 32 tf32 cols -> 128B rows. Stage: A@0 (16K), B@16K. 32KB/stage.
#define STAGE_BYTES 32768
#define NSTAGE 3

__device__ __forceinline__ uint32_t su32(const void* p) {
    uint32_t a;
    asm("{ .reg .u64 t; cvta.to.shared.u64 t, %1; cvt.u32.u64 %0, t; }"
        : "=r"(a) : "l"(p));
    return a;
}

__device__ __forceinline__ float totf(float v) {
    uint32_t r;
    asm("cvt.rna.tf32.f32 %0, %1;" : "=r"(r) : "f"(v));
    return __uint_as_float(r);
}

__device__ __forceinline__ void ldsm4(uint32_t* r, uint32_t addr) {
    asm volatile("ldmatrix.sync.aligned.m8n8.x4.shared.b16 {%0,%1,%2,%3}, [%4];"
                 : "=r"(r[0]), "=r"(r[1]), "=r"(r[2]), "=r"(r[3]) : "r"(addr));
}

__device__ __forceinline__ void mma_tf32(float* d, const uint32_t* a,
                                         uint32_t b0, uint32_t b1) {
    asm volatile(
        "mma.sync.aligned.m16n8k8.row.col.f32.tf32.tf32.f32 "
        "{%0,%1,%2,%3}, {%4,%5,%6,%7}, {%8,%9}, {%0,%1,%2,%3};"
        : "+f"(d[0]), "+f"(d[1]), "+f"(d[2]), "+f"(d[3])
        : "r"(a[0]), "r"(a[1]), "r"(a[2]), "r"(a[3]), "r"(b0), "r"(b1));
}

__device__ __forceinline__ void cp_commit() {
    asm volatile("cp.async.commit_group;" ::: "memory");
}
__device__ __forceinline__ void cp_wait1() {
    asm volatile("cp.async.wait_group 1;" ::: "memory");
}
__device__ __forceinline__ void cp_wait0() {
    asm volatile("cp.async.wait_group 0;" ::: "memory");
}

// Async load of one 128-row x 32-col fp32 tile (128B rows, SW128) into SMEM
__device__ __forceinline__ void async_tile(uint32_t dst, const float* src,
                                           int ld, int tid) {
    #pragma unroll
    for (int t = 0; t < 4; t++) {
        const int idx = tid + t * 256;
        const int row = idx >> 3;
        const int c = idx & 7;
        const uint32_t d = dst + SWZ((uint32_t)(row * 128 + c * 16));
        asm volatile("cp.async.cg.shared.global [%0], [%1], 16;"
                     :: "r"(d), "l"(src + (size_t)row * ld + c * 4));
    }
}

__device__ __forceinline__ void load_chunk(uint32_t stage_base,
                                           const float* A, int lda,
                                           const float* B, int ldb,
                                           int kc, int tid) {
    async_tile(stage_base,         A + (size_t)kc * 32, lda, tid);
    async_tile(stage_base + 16384, B + (size_t)kc * 32, ldb, tid);
    cp_commit();
}

// ---------------------------------------------------------------------------
// Warp K-chunk compute: 4 k8 steps, single-pass tf32.
// warp grid: wm in [0,4) -> 32 rows, wn in [0,2) -> 64 cols
// ---------------------------------------------------------------------------
__device__ __forceinline__ void compute_chunk(uint32_t stage_base,
                                              float acc[2][8][4], int lane,
                                              int wm, int wn) {
    const uint32_t a_b = stage_base;
    const uint32_t b_b = stage_base + 16384;
    const int ar = lane & 15;
    const int xo = (lane >> 4) * 16;
    #pragma unroll
    for (int ks = 0; ks < 4; ks++) {
        uint32_t B[4][4];
        #pragma unroll
        for (int p = 0; p < 4; p++)
            ldsm4(B[p], b_b + SWZ((uint32_t)((wn * 64 + p * 16 + ar) * 128 +
                                             ks * 32 + xo)));
        #pragma unroll
        for (int mt = 0; mt < 2; mt++) {
            uint32_t A[4];
            ldsm4(A, a_b + SWZ((uint32_t)((wm * 32 + mt * 16 + ar) * 128 +
                                          ks * 32 + xo)));
            #pragma unroll
            for (int nt = 0; nt < 8; nt++) {
                const int p = nt >> 1, h = nt & 1;
                mma_tf32(acc[mt][nt], A, B[p][h], B[p][2 + h]);
            }
        }
    }
}

// 3-stage pipeline, 2-deep prefetch, ONE barrier per chunk.
// iter kc: wait(kc ready) -> barrier (publishes kc; retires compute kc-1)
//          -> issue load kc+2 into stage (kc+2)%3 (last used by chunk kc-1,
//             whose compute finished before this barrier) -> compute kc.
__device__ __forceinline__ void gemm_pipeline(uint32_t smb, int nchunks,
                                              const float* A, int lda,
                                              const float* B, int ldb,
                                              float acc[2][8][4], int tid,
                                              int lane, int wm, int wn) {
    load_chunk(smb, A, lda, B, ldb, 0, tid);
    if (1 < nchunks) load_chunk(smb + STAGE_BYTES, A, lda, B, ldb, 1, tid);
    int ld_stage = 2, cp_stage = 0;
    for (int kc = 0; kc < nchunks; kc++) {
        if (kc + 1 < nchunks) cp_wait1();
        else                  cp_wait0();
        __syncthreads();
        if (kc + 2 < nchunks) {
            load_chunk(smb + ld_stage * STAGE_BYTES, A, lda, B, ldb, kc + 2, tid);
            if (++ld_stage == NSTAGE) ld_stage = 0;
        }
        compute_chunk(smb + cp_stage * STAGE_BYTES, acc, lane, wm, wn);
        if (++cp_stage == NSTAGE) cp_stage = 0;
    }
}

// ---------------------------------------------------------------------------
// Epilogue. mode 0: plain fp32; mode 1: scores mask+scale; mode 2: tf32 round
// ---------------------------------------------------------------------------
__device__ __forceinline__ void store_acc(float acc[2][8][4], float* dst,
                                          int ld, int m0, int n0, int mode,
                                          int lane, int wm, int wn) {
    #pragma unroll
    for (int mt = 0; mt < 2; mt++)
        #pragma unroll
        for (int nt = 0; nt < 8; nt++) {
            const int row = m0 + wm * 32 + mt * 16 + (lane >> 2);
            const int col = n0 + wn * 64 + nt * 8 + (lane & 3) * 2;
            float2 v0 = {acc[mt][nt][0], acc[mt][nt][1]};
            float2 v1 = {acc[mt][nt][2], acc[mt][nt][3]};
            if (mode == 1) {
                v0.x = (col + 0 > row) ? -1e30f : v0.x * SCALE;
                v0.y = (col + 1 > row) ? -1e30f : v0.y * SCALE;
                v1.x = (col + 0 > row + 8) ? -1e30f : v1.x * SCALE;
                v1.y = (col + 1 > row + 8) ? -1e30f : v1.y * SCALE;
            } else if (mode == 2) {
                v0.x = totf(v0.x); v0.y = totf(v0.y);
                v1.x = totf(v1.x); v1.y = totf(v1.y);
            }
            *(float2*)(dst + (size_t)row * ld + col) = v0;
            *(float2*)(dst + (size_t)(row + 8) * ld + col) = v1;
        }
}

// ---------------------------------------------------------------------------
// Prep kernels
// ---------------------------------------------------------------------------
__global__ void round_x(const float4* __restrict__ x) {
    const size_t i = (size_t)blockIdx.x * blockDim.x + threadIdx.x;
    float4 v = x[i];
    v.x = totf(v.x); v.y = totf(v.y); v.z = totf(v.z); v.w = totf(v.w);
    ((float4*)g_X)[i] = v;
}

__global__ void prep_w(const float* __restrict__ Wq, const float* __restrict__ Wk,
                       const float* __restrict__ Wv) {
    __shared__ float t[32][33];
    const int w = blockIdx.z;
    const float* W = (w == 0) ? Wq : (w == 1) ? Wk : Wv;
    float* o = g_WT + (size_t)w * DIM * DIM;
    const int tx = threadIdx.x, ty = threadIdx.y;
    const int n0 = blockIdx.x * 32, k0 = blockIdx.y * 32;
    #pragma unroll
    for (int i = 0; i < 4; i++)
        t[ty + 8 * i][tx] = W[(size_t)(k0 + ty + 8 * i) * DIM + n0 + tx];
    __syncthreads();
    #pragma unroll
    for (int i = 0; i < 4; i++)
        o[(size_t)(n0 + ty + 8 * i) * DIM + k0 + tx] = totf(t[tx][ty + 8 * i]);
}

__global__ void prep_vT() {
    __shared__ float t[32][33];
    const int b = blockIdx.z;
    const float* V = g_V + (size_t)b * SEQ * DIM;
    float* o = g_VT + (size_t)b * DIM * SEQ;
    const int tx = threadIdx.x, ty = threadIdx.y;
    const int d0 = blockIdx.x * 32, s0 = blockIdx.y * 32;
    #pragma unroll
    for (int i = 0; i < 4; i++)
        t[ty + 8 * i][tx] = V[(size_t)(s0 + ty + 8 * i) * DIM + d0 + tx];
    __syncthreads();
    #pragma unroll
    for (int i = 0; i < 4; i++)
        o[(size_t)(d0 + ty + 8 * i) * SEQ + s0 + tx] = t[tx][ty + 8 * i];
}

// ---------------------------------------------------------------------------
// GEMM 1: QKV projection -> tf32-rounded Q/K/V
// ---------------------------------------------------------------------------
__global__ void __launch_bounds__(256, 2) qkv_tf() {
    extern __shared__ uint8_t dsm[];
    const uint32_t smb = su32(dsm);
    const int tid = threadIdx.x;
    const int lane = tid & 31;
    const int wid = tid >> 5;
    const int wm = wid & 3, wn = wid >> 2;

    const int w = blockIdx.z;
    const int m0 = blockIdx.y * 128;
    const int n0 = blockIdx.x * 128;
    const float* A = g_X + (size_t)m0 * DIM;
    const float* B = g_WT + (size_t)w * DIM * DIM + (size_t)n0 * DIM;
    float* C = (w == 0) ? g_Q : (w == 1) ? g_K : g_V;

    float acc[2][8][4] = {};
    gemm_pipeline(smb, DIM / 32, A, DIM, B, DIM, acc, tid, lane, wm, wn);
    store_acc(acc, C, DIM, m0, n0, 2, lane, wm, wn);
}

// ---------------------------------------------------------------------------
// GEMM 2: scores = scale * Q @ K^T, causal mask fused
// ---------------------------------------------------------------------------
__global__ void __launch_bounds__(256, 2) scores_tf() {
    const int kt = blockIdx.x;
    const int qt = blockIdx.y;
    if (kt > qt) return;
    extern __shared__ uint8_t dsm[];
    const uint32_t smb = su32(dsm);
    const int tid = threadIdx.x;
    const int lane = tid & 31;
    const int wid = tid >> 5;
    const int wm = wid & 3, wn = wid >> 2;

    const int b = blockIdx.z;
    const int m0 = qt * 128;
    const int n0 = kt * 128;
    const float* A = g_Q + (size_t)(b * SEQ + m0) * DIM;
    const float* B = g_K + (size_t)(b * SEQ + n0) * DIM;

    float acc[2][8][4] = {};
    gemm_pipeline(smb, DIM / 32, A, DIM, B, DIM, acc, tid, lane, wm, wn);
    store_acc(acc, g_S + (size_t)b * SEQ * SEQ, SEQ, m0, n0, 1, lane, wm, wn);
}

// ---------------------------------------------------------------------------
// Kernel 3: row softmax -> tf32-rounded P
// ---------------------------------------------------------------------------
__global__ void __launch_bounds__(256) softmax_rows() {
    const int q = blockIdx.x;
    const int b = blockIdx.y;
    const size_t base = (size_t)b * SEQ * SEQ + (size_t)q * SEQ;
    const float* row = g_S + base;
    const int L = ((q >> 7) + 1) << 7;

    const int tid = threadIdx.x;
    __shared__ float red[256];

    float vals[8];
    int cnt = 0;
    float m = -1e30f;
    for (int idx = tid; idx < L; idx += 256) {
        vals[cnt] = row[idx];
        m = fmaxf(m, vals[cnt]);
        cnt++;
    }
    red[tid] = m;
    __syncthreads();
    #pragma unroll
    for (int s = 128; s > 0; s >>= 1) {
        if (tid < s) red[tid] = fmaxf(red[tid], red[tid + s]);
        __syncthreads();
    }
    const float M = red[0];
    __syncthreads();

    float sum = 0.f;
    for (int i = 0; i < cnt; i++) {
        vals[i] = __expf(vals[i] - M);
        sum += vals[i];
    }
    red[tid] = sum;
    __syncthreads();
    #pragma unroll
    for (int s = 128; s > 0; s >>= 1) {
        if (tid < s) red[tid] += red[tid + s];
        __syncthreads();
    }
    const float inv = 1.0f / red[0];

    cnt = 0;
    for (int idx = tid; idx < L; idx += 256)
        g_P[base + idx] = totf(vals[cnt++] * inv);
}

// ---------------------------------------------------------------------------
// GEMM 4: O = P @ V, causal K-extent, heavy q-tiles first
// ---------------------------------------------------------------------------
__global__ void __launch_bounds__(256, 2) pv_tf(float* __restrict__ out) {
    extern __shared__ uint8_t dsm[];
    const uint32_t smb = su32(dsm);
    const int tid = threadIdx.x;
    const int lane = tid & 31;
    const int wid = tid >> 5;
    const int wm = wid & 3, wn = wid >> 2;

    const int et = blockIdx.x;
    const int qt = (SEQ / 128 - 1) - blockIdx.y;   // heavy tiles first
    const int b  = blockIdx.z;
    const int m0 = qt * 128;
    const int n0 = et * 128;
    const int nchunks = (qt + 1) * 4;   // K-extent (qt+1)*128 / 32

    const float* A = g_P + (size_t)b * SEQ * SEQ + (size_t)m0 * SEQ;
    const float* B = g_VT + (size_t)b * DIM * SEQ + (size_t)n0 * SEQ;

    float acc[2][8][4] = {};
    gemm_pipeline(smb, nchunks, A, SEQ, B, SEQ, acc, tid, lane, wm, wn);
    store_acc(acc, out + (size_t)b * SEQ * DIM, DIM, m0, n0, 0, lane, wm, wn);
}

// ---------------------------------------------------------------------------
extern "C" void kernel_launch(void* const* d_in, const int* in_sizes, int n_in,
                              void* d_out, int out_size) {
    const float* x  = (const float*)d_in[0];
    const float* Wq = (const float*)d_in[1];
    const float* Wk = (const float*)d_in[2];
    const float* Wv = (const float*)d_in[3];
    float* out = (float*)d_out;

    const int DSM = NSTAGE * STAGE_BYTES;  // 96KB -> 2 CTAs/SM
    static bool attr_done = false;
    if (!attr_done) {
        cudaFuncSetAttribute(qkv_tf, cudaFuncAttributeMaxDynamicSharedMemorySize, DSM);
        cudaFuncSetAttribute(scores_tf, cudaFuncAttributeMaxDynamicSharedMemorySize, DSM);
        cudaFuncSetAttribute(pv_tf, cudaFuncAttributeMaxDynamicSharedMemorySize, DSM);
        attr_done = true;
    }

    round_x<<<(MTOT * DIM / 4) / 256, 256>>>((const float4*)x);
    prep_w<<<dim3(DIM / 32, DIM / 32, 3), dim3(32, 8)>>>(Wq, Wk, Wv);
    qkv_tf<<<dim3(DIM / 128, MTOT / 128, 3), 256, DSM>>>();
    prep_vT<<<dim3(DIM / 32, SEQ / 32, BATCH), dim3(32, 8)>>>();
    scores_tf<<<dim3(SEQ / 128, SEQ / 128, BATCH), 256, DSM>>>();
    softmax_rows<<<dim3(SEQ, BATCH), 256>>>();
    pv_tf<<<dim3(DIM / 128, SEQ / 128, BATCH), 256, DSM>>>(out);
}

// round 15
// speedup vs baseline: 3.8435x; 1.0071x over previous
#include <cuda_runtime.h>
#include <stdint.h>
#include <math.h>

#define BATCH 4
#define SEQ   2048
#define DIM   1024
#define MTOT  (BATCH * SEQ)   // 8192
#define SCALE 0.03125f        // 1/sqrt(1024)

// ---------------------------------------------------------------------------
// Device-global scratch (allocation-guard safe) — all fp32 (tf32-rounded)
// ---------------------------------------------------------------------------
__device__ float g_X [(size_t)MTOT * DIM];                 // rounded x [m][k]
__device__ float g_WT[(size_t)3 * DIM * DIM];              // rounded W^T [w][n][k]
__device__ float g_Q [(size_t)MTOT * DIM];                 // rounded
__device__ float g_K [(size_t)MTOT * DIM];                 // rounded
__device__ float g_V [(size_t)MTOT * DIM];                 // rounded
__device__ float g_VT[(size_t)BATCH * DIM * SEQ];          // V^T [b][d][s]
__device__ float g_S [(size_t)BATCH * SEQ * SEQ];          // raw scores
__device__ float g_P [(size_t)BATCH * SEQ * SEQ];          // rounded softmax

#define SWZ(o) ((o) ^ (((o) >> 3) & 0x70))
// K-chunk = 32 tf32 cols -> 128B rows. Stage: A@0 (16K), B@16K. 32KB/stage.
#define STAGE_BYTES 32768
#define NSTAGE 3
#define NTHREADS 128    // 4 warps, each 64x64

__device__ __forceinline__ uint32_t su32(const void* p) {
    uint32_t a;
    asm("{ .reg .u64 t; cvta.to.shared.u64 t, %1; cvt.u32.u64 %0, t; }"
        : "=r"(a) : "l"(p));
    return a;
}

__device__ __forceinline__ float totf(float v) {
    uint32_t r;
    asm("cvt.rna.tf32.f32 %0, %1;" : "=r"(r) : "f"(v));
    return __uint_as_float(r);
}

__device__ __forceinline__ void ldsm4(uint32_t* r, uint32_t addr) {
    asm volatile("ldmatrix.sync.aligned.m8n8.x4.shared.b16 {%0,%1,%2,%3}, [%4];"
                 : "=r"(r[0]), "=r"(r[1]), "=r"(r[2]), "=r"(r[3]) : "r"(addr));
}

__device__ __forceinline__ void mma_tf32(float* d, const uint32_t* a,
                                         uint32_t b0, uint32_t b1) {
    asm volatile(
        "mma.sync.aligned.m16n8k8.row.col.f32.tf32.tf32.f32 "
        "{%0,%1,%2,%3}, {%4,%5,%6,%7}, {%8,%9}, {%0,%1,%2,%3};"
        : "+f"(d[0]), "+f"(d[1]), "+f"(d[2]), "+f"(d[3])
        : "r"(a[0]), "r"(a[1]), "r"(a[2]), "r"(a[3]), "r"(b0), "r"(b1));
}

__device__ __forceinline__ void cp_commit() {
    asm volatile("cp.async.commit_group;" ::: "memory");
}
__device__ __forceinline__ void cp_wait1() {
    asm volatile("cp.async.wait_group 1;" ::: "memory");
}
__device__ __forceinline__ void cp_wait0() {
    asm volatile("cp.async.wait_group 0;" ::: "memory");
}

// Async load of one 128-row x 32-col fp32 tile (128B rows, SW128) into SMEM
__device__ __forceinline__ void async_tile(uint32_t dst, const float* src,
                                           int ld, int tid) {
    #pragma unroll
    for (int t = 0; t < 8; t++) {
        const int idx = tid + t * NTHREADS;   // 0..1023
        const int row = idx >> 3;
        const int c = idx & 7;
        const uint32_t d = dst + SWZ((uint32_t)(row * 128 + c * 16));
        asm volatile("cp.async.cg.shared.global [%0], [%1], 16;"
                     :: "r"(d), "l"(src + (size_t)row * ld + c * 4));
    }
}

__device__ __forceinline__ void load_chunk(uint32_t stage_base,
                                           const float* A, int lda,
                                           const float* B, int ldb,
                                           int kc, int tid) {
    async_tile(stage_base,         A + (size_t)kc * 32, lda, tid);
    async_tile(stage_base + 16384, B + (size_t)kc * 32, ldb, tid);
    cp_commit();
}

// ---------------------------------------------------------------------------
// Warp K-chunk compute: 64x64 warp tile, 4 k8 steps, single-pass tf32.
// warp grid: wm in [0,2) -> 64 rows, wn in [0,2) -> 64 cols.
// Per ks: 4 B LDSM.x4 + 4 A LDSM.x4 -> 32 MMAs  (128B smem per MMA)
// ---------------------------------------------------------------------------
__device__ __forceinline__ void compute_chunk(uint32_t stage_base,
                                              float acc[4][8][4], int lane,
                                              int wm, int wn) {
    const uint32_t a_b = stage_base;
    const uint32_t b_b = stage_base + 16384;
    const int ar = lane & 15;
    const int xo = (lane >> 4) * 16;
    #pragma unroll
    for (int ks = 0; ks < 4; ks++) {
        uint32_t B[4][4];
        #pragma unroll
        for (int p = 0; p < 4; p++)
            ldsm4(B[p], b_b + SWZ((uint32_t)((wn * 64 + p * 16 + ar) * 128 +
                                             ks * 32 + xo)));
        #pragma unroll
        for (int mt = 0; mt < 4; mt++) {
            uint32_t A[4];
            ldsm4(A, a_b + SWZ((uint32_t)((wm * 64 + mt * 16 + ar) * 128 +
                                          ks * 32 + xo)));
            #pragma unroll
            for (int nt = 0; nt < 8; nt++) {
                const int p = nt >> 1, h = nt & 1;
                mma_tf32(acc[mt][nt], A, B[p][h], B[p][2 + h]);
            }
        }
    }
}

// 3-stage pipeline, 2-deep prefetch, ONE barrier per chunk.
__device__ __forceinline__ void gemm_pipeline(uint32_t smb, int nchunks,
                                              const float* A, int lda,
                                              const float* B, int ldb,
                                              float acc[4][8][4], int tid,
                                              int lane, int wm, int wn) {
    load_chunk(smb, A, lda, B, ldb, 0, tid);
    if (1 < nchunks) load_chunk(smb + STAGE_BYTES, A, lda, B, ldb, 1, tid);
    int ld_stage = 2, cp_stage = 0;
    for (int kc = 0; kc < nchunks; kc++) {
        if (kc + 1 < nchunks) cp_wait1();
        else                  cp_wait0();
        __syncthreads();
        if (kc + 2 < nchunks) {
            load_chunk(smb + ld_stage * STAGE_BYTES, A, lda, B, ldb, kc + 2, tid);
            if (++ld_stage == NSTAGE) ld_stage = 0;
        }
        compute_chunk(smb + cp_stage * STAGE_BYTES, acc, lane, wm, wn);
        if (++cp_stage == NSTAGE) cp_stage = 0;
    }
}

// ---------------------------------------------------------------------------
// Epilogue. mode 0: plain fp32; mode 1: scores mask+scale; mode 2: tf32 round
// ---------------------------------------------------------------------------
__device__ __forceinline__ void store_acc(float acc[4][8][4], float* dst,
                                          int ld, int m0, int n0, int mode,
                                          int lane, int wm, int wn) {
    #pragma unroll
    for (int mt = 0; mt < 4; mt++)
        #pragma unroll
        for (int nt = 0; nt < 8; nt++) {
            const int row = m0 + wm * 64 + mt * 16 + (lane >> 2);
            const int col = n0 + wn * 64 + nt * 8 + (lane & 3) * 2;
            float2 v0 = {acc[mt][nt][0], acc[mt][nt][1]};
            float2 v1 = {acc[mt][nt][2], acc[mt][nt][3]};
            if (mode == 1) {
                v0.x = (col + 0 > row) ? -1e30f : v0.x * SCALE;
                v0.y = (col + 1 > row) ? -1e30f : v0.y * SCALE;
                v1.x = (col + 0 > row + 8) ? -1e30f : v1.x * SCALE;
                v1.y = (col + 1 > row + 8) ? -1e30f : v1.y * SCALE;
            } else if (mode == 2) {
                v0.x = totf(v0.x); v0.y = totf(v0.y);
                v1.x = totf(v1.x); v1.y = totf(v1.y);
            }
            *(float2*)(dst + (size_t)row * ld + col) = v0;
            *(float2*)(dst + (size_t)(row + 8) * ld + col) = v1;
        }
}

// ---------------------------------------------------------------------------
// Prep kernels
// ---------------------------------------------------------------------------
__global__ void round_x(const float4* __restrict__ x) {
    const size_t i = (size_t)blockIdx.x * blockDim.x + threadIdx.x;
    float4 v = x[i];
    v.x = totf(v.x); v.y = totf(v.y); v.z = totf(v.z); v.w = totf(v.w);
    ((float4*)g_X)[i] = v;
}

__global__ void prep_w(const float* __restrict__ Wq, const float* __restrict__ Wk,
                       const float* __restrict__ Wv) {
    __shared__ float t[32][33];
    const int w = blockIdx.z;
    const float* W = (w == 0) ? Wq : (w == 1) ? Wk : Wv;
    float* o = g_WT + (size_t)w * DIM * DIM;
    const int tx = threadIdx.x, ty = threadIdx.y;
    const int n0 = blockIdx.x * 32, k0 = blockIdx.y * 32;
    #pragma unroll
    for (int i = 0; i < 4; i++)
        t[ty + 8 * i][tx] = W[(size_t)(k0 + ty + 8 * i) * DIM + n0 + tx];
    __syncthreads();
    #pragma unroll
    for (int i = 0; i < 4; i++)
        o[(size_t)(n0 + ty + 8 * i) * DIM + k0 + tx] = totf(t[tx][ty + 8 * i]);
}

__global__ void prep_vT() {
    __shared__ float t[32][33];
    const int b = blockIdx.z;
    const float* V = g_V + (size_t)b * SEQ * DIM;
    float* o = g_VT + (size_t)b * DIM * SEQ;
    const int tx = threadIdx.x, ty = threadIdx.y;
    const int d0 = blockIdx.x * 32, s0 = blockIdx.y * 32;
    #pragma unroll
    for (int i = 0; i < 4; i++)
        t[ty + 8 * i][tx] = V[(size_t)(s0 + ty + 8 * i) * DIM + d0 + tx];
    __syncthreads();
    #pragma unroll
    for (int i = 0; i < 4; i++)
        o[(size_t)(d0 + ty + 8 * i) * SEQ + s0 + tx] = t[tx][ty + 8 * i];
}

// ---------------------------------------------------------------------------
// GEMM 1: QKV projection -> tf32-rounded Q/K/V
// ---------------------------------------------------------------------------
__global__ void __launch_bounds__(NTHREADS, 2) qkv_tf() {
    extern __shared__ uint8_t dsm[];
    const uint32_t smb = su32(dsm);
    const int tid = threadIdx.x;
    const int lane = tid & 31;
    const int wid = tid >> 5;
    const int wm = wid & 1, wn = wid >> 1;

    const int w = blockIdx.z;
    const int m0 = blockIdx.y * 128;
    const int n0 = blockIdx.x * 128;
    const float* A = g_X + (size_t)m0 * DIM;
    const float* B = g_WT + (size_t)w * DIM * DIM + (size_t)n0 * DIM;
    float* C = (w == 0) ? g_Q : (w == 1) ? g_K : g_V;

    float acc[4][8][4] = {};
    gemm_pipeline(smb, DIM / 32, A, DIM, B, DIM, acc, tid, lane, wm, wn);
    store_acc(acc, C, DIM, m0, n0, 2, lane, wm, wn);
}

// ---------------------------------------------------------------------------
// GEMM 2: scores = scale * Q @ K^T, causal mask fused
// ---------------------------------------------------------------------------
__global__ void __launch_bounds__(NTHREADS, 2) scores_tf() {
    const int kt = blockIdx.x;
    const int qt = blockIdx.y;
    if (kt > qt) return;
    extern __shared__ uint8_t dsm[];
    const uint32_t smb = su32(dsm);
    const int tid = threadIdx.x;
    const int lane = tid & 31;
    const int wid = tid >> 5;
    const int wm = wid & 1, wn = wid >> 1;

    const int b = blockIdx.z;
    const int m0 = qt * 128;
    const int n0 = kt * 128;
    const float* A = g_Q + (size_t)(b * SEQ + m0) * DIM;
    const float* B = g_K + (size_t)(b * SEQ + n0) * DIM;

    float acc[4][8][4] = {};
    gemm_pipeline(smb, DIM / 32, A, DIM, B, DIM, acc, tid, lane, wm, wn);
    store_acc(acc, g_S + (size_t)b * SEQ * SEQ, SEQ, m0, n0, 1, lane, wm, wn);
}

// ---------------------------------------------------------------------------
// Kernel 3: row softmax -> tf32-rounded P
// ---------------------------------------------------------------------------
__global__ void __launch_bounds__(256) softmax_rows() {
    const int q = blockIdx.x;
    const int b = blockIdx.y;
    const size_t base = (size_t)b * SEQ * SEQ + (size_t)q * SEQ;
    const float* row = g_S + base;
    const int L = ((q >> 7) + 1) << 7;

    const int tid = threadIdx.x;
    __shared__ float red[256];

    float vals[8];
    int cnt = 0;
    float m = -1e30f;
    for (int idx = tid; idx < L; idx += 256) {
        vals[cnt] = row[idx];
        m = fmaxf(m, vals[cnt]);
        cnt++;
    }
    red[tid] = m;
    __syncthreads();
    #pragma unroll
    for (int s = 128; s > 0; s >>= 1) {
        if (tid < s) red[tid] = fmaxf(red[tid], red[tid + s]);
        __syncthreads();
    }
    const float M = red[0];
    __syncthreads();

    float sum = 0.f;
    for (int i = 0; i < cnt; i++) {
        vals[i] = __expf(vals[i] - M);
        sum += vals[i];
    }
    red[tid] = sum;
    __syncthreads();
    #pragma unroll
    for (int s = 128; s > 0; s >>= 1) {
        if (tid < s) red[tid] += red[tid + s];
        __syncthreads();
    }
    const float inv = 1.0f / red[0];

    cnt = 0;
    for (int idx = tid; idx < L; idx += 256)
        g_P[base + idx] = totf(vals[cnt++] * inv);
}

// ---------------------------------------------------------------------------
// GEMM 4: O = P @ V, causal K-extent, heavy q-tiles first
// ---------------------------------------------------------------------------
__global__ void __launch_bounds__(NTHREADS, 2) pv_tf(float* __restrict__ out) {
    extern __shared__ uint8_t dsm[];
    const uint32_t smb = su32(dsm);
    const int tid = threadIdx.x;
    const int lane = tid & 31;
    const int wid = tid >> 5;
    const int wm = wid & 1, wn = wid >> 1;

    const int et = blockIdx.x;
    const int qt = (SEQ / 128 - 1) - blockIdx.y;   // heavy tiles first
    const int b  = blockIdx.z;
    const int m0 = qt * 128;
    const int n0 = et * 128;
    const int nchunks = (qt + 1) * 4;   // K-extent (qt+1)*128 / 32

    const float* A = g_P + (size_t)b * SEQ * SEQ + (size_t)m0 * SEQ;
    const float* B = g_VT + (size_t)b * DIM * SEQ + (size_t)n0 * SEQ;

    float acc[4][8][4] = {};
    gemm_pipeline(smb, nchunks, A, SEQ, B, SEQ, acc, tid, lane, wm, wn);
    store_acc(acc, out + (size_t)b * SEQ * DIM, DIM, m0, n0, 0, lane, wm, wn);
}

// ---------------------------------------------------------------------------
extern "C" void kernel_launch(void* const* d_in, const int* in_sizes, int n_in,
                              void* d_out, int out_size) {
    const float* x  = (const float*)d_in[0];
    const float* Wq = (const float*)d_in[1];
    const float* Wk = (const float*)d_in[2];
    const float* Wv = (const float*)d_in[3];
    float* out = (float*)d_out;

    const int DSM = NSTAGE * STAGE_BYTES;  // 96KB -> 2 CTAs/SM
    static bool attr_done = false;
    if (!attr_done) {
        cudaFuncSetAttribute(qkv_tf, cudaFuncAttributeMaxDynamicSharedMemorySize, DSM);
        cudaFuncSetAttribute(scores_tf, cudaFuncAttributeMaxDynamicSharedMemorySize, DSM);
        cudaFuncSetAttribute(pv_tf, cudaFuncAttributeMaxDynamicSharedMemorySize, DSM);
        attr_done = true;
    }

    round_x<<<(MTOT * DIM / 4) / 256, 256>>>((const float4*)x);
    prep_w<<<dim3(DIM / 32, DIM / 32, 3), dim3(32, 8)>>>(Wq, Wk, Wv);
    qkv_tf<<<dim3(DIM / 128, MTOT / 128, 3), NTHREADS, DSM>>>();
    prep_vT<<<dim3(DIM / 32, SEQ / 32, BATCH), dim3(32, 8)>>>();
    scores_tf<<<dim3(SEQ / 128, SEQ / 128, BATCH), NTHREADS, DSM>>>();
    softmax_rows<<<dim3(SEQ, BATCH), 256>>>();
    pv_tf<<<dim3(DIM / 128, SEQ / 128, BATCH), NTHREADS, DSM>>>(out);
}